// round 6
// baseline (speedup 1.0000x reference)
#include <cuda_runtime.h>

// Adaptive avg pool (32,50,50,768) NHWC -> (32,7,7,768), fp32.
// All H/W windows are [7*o, 7*o+8) (size 8, stride 7), avg over 64 elems.
//
// R6: R5 scheme (one thread per output float4; 1176 CTAs x 256 thr = single
// wave at 8 CTAs/SM; 32 regs; boundary-rows-first for L2 dedup of H-shared
// rows; __ldcs streaming interior) + cache-policy tuning:
//   - boundary rows via __ldcg (L2-resident, L1-bypass — no L1 reuse exists)
//   - output via __stcs (streaming writeback, don't pollute L2)

#define HIN  50
#define WIN  50
#define CV   192   // 768 / 4 float4 lanes per pixel
#define HO   7
#define WO   7

__global__ __launch_bounds__(256, 8)
void adaptive_pool_flat(const float4* __restrict__ in4, float4* __restrict__ out4) {
    // virtual 64-thread group id: 4 per CTA
    const int virt = blockIdx.x * 4 + (threadIdx.x >> 6);  // 0..4703
    const int lane = threadIdx.x & 63;
    const int cseg = virt % 3;
    const int t    = virt / 3;          // 0..1567 = (b*7+oh)*7+ow
    const int ow   = t % WO;
    const int u    = t / WO;            // b*7+oh
    const int oh   = u % HO;
    const int b    = u / HO;
    const int cvec = cseg * 64 + lane;

    const int h0 = oh * 7;
    const int w0 = ow * 7;

    float4 acc = make_float4(0.f, 0.f, 0.f, 0.f);

    const float4* base = in4 + ((size_t)(b * HIN + h0) * WIN + w0) * CV + cvec;

    // Boundary rows first (7 then 0): shared with adjacent-oh windows; both
    // sharers touch them at nearly the same time -> L2 dedup. __ldcg keeps
    // them in L2 but skips useless L1 allocation.
    #pragma unroll
    for (int c = 0; c < 8; ++c) {
        float4 v = __ldcg(&base[(size_t)(7 * WIN + c) * CV]);
        acc.x += v.x; acc.y += v.y; acc.z += v.z; acc.w += v.w;
    }
    #pragma unroll
    for (int c = 0; c < 8; ++c) {
        float4 v = __ldcg(&base[(size_t)c * CV]);
        acc.x += v.x; acc.y += v.y; acc.z += v.z; acc.w += v.w;
    }

    // Interior rows 1..6: read exactly once chip-wide -> streaming loads.
    #pragma unroll
    for (int r = 1; r < 7; ++r) {
        const float4* row = base + (size_t)r * (WIN * CV);
        #pragma unroll
        for (int c = 0; c < 8; ++c) {
            float4 v = __ldcs(&row[(size_t)c * CV]);
            acc.x += v.x; acc.y += v.y; acc.z += v.z; acc.w += v.w;
        }
    }

    const float s = 1.0f / 64.0f;
    acc.x *= s; acc.y *= s; acc.z *= s; acc.w *= s;
    __stcs(&out4[(size_t)t * CV + cvec], acc);
}

extern "C" void kernel_launch(void* const* d_in, const int* in_sizes, int n_in,
                              void* d_out, int out_size) {
    const float4* in4 = (const float4*)d_in[0];
    float4* out4 = (float4*)d_out;
    adaptive_pool_flat<<<(32 * HO * WO * 3) / 4, 256>>>(in4, out4);
}

// round 7
// speedup vs baseline: 1.0025x; 1.0025x over previous
#include <cuda_runtime.h>

// Adaptive avg pool (32,50,50,768) NHWC -> (32,7,7,768), fp32.
// All H/W windows are [7*o, 7*o+8) (size 8, stride 7), avg over 64 elems.
//
// R7 (final): proven R6 scheme — one thread per output float4, 32 regs,
// boundary-rows-first ordering (L2 dedup of H-shared rows, -29.5 MB DRAM),
// __ldcg boundary / __ldcs interior / __stcs output — with one more CTA
// consolidation: 588 CTAs x 512 threads <= 148 SMs x 4 CTAs -> single wave,
// minimal dispatch overhead, 8KB-contiguous per-step CTA footprint.
// Kernel is at the practical HBM ceiling (traffic == unique 251 MB,
// occ 95%, BW plateau ~6.4 TB/s across schedules).

#define HIN  50
#define WIN  50
#define CV   192   // 768 / 4 float4 lanes per pixel
#define HO   7
#define WO   7

__global__ __launch_bounds__(512, 4)
void adaptive_pool_flat(const float4* __restrict__ in4, float4* __restrict__ out4) {
    // virtual 64-thread group id: 8 per CTA
    const int virt = blockIdx.x * 8 + (threadIdx.x >> 6);  // 0..4703
    const int lane = threadIdx.x & 63;
    const int cseg = virt % 3;
    const int t    = virt / 3;          // 0..1567 = (b*7+oh)*7+ow
    const int ow   = t % WO;
    const int u    = t / WO;            // b*7+oh
    const int oh   = u % HO;
    const int b    = u / HO;
    const int cvec = cseg * 64 + lane;

    const int h0 = oh * 7;
    const int w0 = ow * 7;

    float4 acc = make_float4(0.f, 0.f, 0.f, 0.f);

    const float4* base = in4 + ((size_t)(b * HIN + h0) * WIN + w0) * CV + cvec;

    // Boundary rows first (7 then 0): shared with adjacent-oh windows; both
    // sharers touch them at nearly the same time -> L2 dedup. __ldcg keeps
    // them in L2 but skips useless L1 allocation.
    #pragma unroll
    for (int c = 0; c < 8; ++c) {
        float4 v = __ldcg(&base[(size_t)(7 * WIN + c) * CV]);
        acc.x += v.x; acc.y += v.y; acc.z += v.z; acc.w += v.w;
    }
    #pragma unroll
    for (int c = 0; c < 8; ++c) {
        float4 v = __ldcg(&base[(size_t)c * CV]);
        acc.x += v.x; acc.y += v.y; acc.z += v.z; acc.w += v.w;
    }

    // Interior rows 1..6: read exactly once chip-wide -> streaming loads.
    #pragma unroll
    for (int r = 1; r < 7; ++r) {
        const float4* row = base + (size_t)r * (WIN * CV);
        #pragma unroll
        for (int c = 0; c < 8; ++c) {
            float4 v = __ldcs(&row[(size_t)c * CV]);
            acc.x += v.x; acc.y += v.y; acc.z += v.z; acc.w += v.w;
        }
    }

    const float s = 1.0f / 64.0f;
    acc.x *= s; acc.y *= s; acc.z *= s; acc.w *= s;
    __stcs(&out4[(size_t)t * CV + cvec], acc);
}

extern "C" void kernel_launch(void* const* d_in, const int* in_sizes, int n_in,
                              void* d_out, int out_size) {
    const float4* in4 = (const float4*)d_in[0];
    float4* out4 = (float4*)d_out;
    adaptive_pool_flat<<<(32 * HO * WO * 3) / 8, 512>>>(in4, out4);
}

// round 8
// speedup vs baseline: 1.0437x; 1.0411x over previous
#include <cuda_runtime.h>

// Adaptive avg pool (32,50,50,768) NHWC -> (32,7,7,768), fp32.  FINAL.
// All H/W windows are [7*o, 7*o+8) (size 8, stride 7), avg over 64 elems.
//
// Design (converged over R3-R7):
//  - one thread per output float4: 4704 virtual 64-thread groups, packed
//    into 588 CTAs x 512 threads <= 148 SMs x 4 CTAs -> exactly one wave
//    (no tail; the single wave is effectively a persistent launch)
//  - 32 regs/thread (launch_bounds) -> full 2048-thread SM residency
//  - 64 independent LDG.128 per thread -> ample MLP for DRAM latency
//  - boundary rows (r=7 then r=0) read FIRST: both adjacent-oh sharers
//    touch them nearly simultaneously -> L2 dedup (-29.5 MB DRAM traffic,
//    measured), __ldcg skips useless L1 allocation
//  - interior rows r=1..6 (read exactly once chip-wide) via __ldcs
//    streaming; output via __stcs -> no L2 pollution
// Measured: 38.9 us, DRAM traffic == 251 MB unique floor, ~6.4 TB/s
// effective HBM BW = practical ceiling (plateau across schedules).

#define HIN  50
#define WIN  50
#define CV   192   // 768 / 4 float4 lanes per pixel
#define HO   7
#define WO   7

__global__ __launch_bounds__(512, 4)
void adaptive_pool_flat(const float4* __restrict__ in4, float4* __restrict__ out4) {
    // virtual 64-thread group id: 8 per CTA
    const int virt = blockIdx.x * 8 + (threadIdx.x >> 6);  // 0..4703
    const int lane = threadIdx.x & 63;
    const int cseg = virt % 3;
    const int t    = virt / 3;          // 0..1567 = (b*7+oh)*7+ow
    const int ow   = t % WO;
    const int u    = t / WO;            // b*7+oh
    const int oh   = u % HO;
    const int b    = u / HO;
    const int cvec = cseg * 64 + lane;

    const int h0 = oh * 7;
    const int w0 = ow * 7;

    float4 acc = make_float4(0.f, 0.f, 0.f, 0.f);

    const float4* base = in4 + ((size_t)(b * HIN + h0) * WIN + w0) * CV + cvec;

    // Boundary rows first (7 then 0): shared with adjacent-oh windows ->
    // near-simultaneous touch by both sharers -> L2 dedup. __ldcg keeps
    // them L2-resident without L1 allocation.
    #pragma unroll
    for (int c = 0; c < 8; ++c) {
        float4 v = __ldcg(&base[(size_t)(7 * WIN + c) * CV]);
        acc.x += v.x; acc.y += v.y; acc.z += v.z; acc.w += v.w;
    }
    #pragma unroll
    for (int c = 0; c < 8; ++c) {
        float4 v = __ldcg(&base[(size_t)c * CV]);
        acc.x += v.x; acc.y += v.y; acc.z += v.z; acc.w += v.w;
    }

    // Interior rows 1..6: read exactly once chip-wide -> streaming loads.
    #pragma unroll
    for (int r = 1; r < 7; ++r) {
        const float4* row = base + (size_t)r * (WIN * CV);
        #pragma unroll
        for (int c = 0; c < 8; ++c) {
            float4 v = __ldcs(&row[(size_t)c * CV]);
            acc.x += v.x; acc.y += v.y; acc.z += v.z; acc.w += v.w;
        }
    }

    const float s = 1.0f / 64.0f;
    acc.x *= s; acc.y *= s; acc.z *= s; acc.w *= s;
    __stcs(&out4[(size_t)t * CV + cvec], acc);
}

extern "C" void kernel_launch(void* const* d_in, const int* in_sizes, int n_in,
                              void* d_out, int out_size) {
    const float4* in4 = (const float4*)d_in[0];
    float4* out4 = (float4*)d_out;
    adaptive_pool_flat<<<(32 * HO * WO * 3) / 8, 512>>>(in4, out4);
}